// round 14
// baseline (speedup 1.0000x reference)
#include <cuda_runtime.h>

#define BB 16
#define NN 4096
#define SS 1024
#define NSAMP 32
#define MM (BB*SS*NSAMP)  // 524288
#define MAXBLK 8192

// ---------------- scratch (__device__ globals: no allocations allowed) ----
__device__ float g_cent[BB*SS*3];
__device__ float g_h0[64*MM];    // 134 MB
__device__ float g_h1[64*MM];    // 134 MB
__device__ float g_max[128*16384];
__device__ float g_part_s[128*MAXBLK];
__device__ float g_part_q[128*MAXBLK];
__device__ float g_scale[256];
__device__ float g_shift[256];

// packed f32x2 helpers (per-element IEEE rn — bit-identical to scalar rn ops)
#define PACKF2(o,a,b)  asm("mov.b64 %0,{%1,%2};"       : "=l"(o) : "f"(a), "f"(b))
#define UNPACKF2(a,b,i) asm("mov.b64 {%0,%1},%2;"      : "=f"(a), "=f"(b) : "l"(i))
#define ADDF2(o,a,b)   asm("add.rn.f32x2 %0,%1,%2;"    : "=l"(o) : "l"(a), "l"(b))
#define MULF2(o,a,b)   asm("mul.rn.f32x2 %0,%1,%2;"    : "=l"(o) : "l"(a), "l"(b))
#define FMAF2(d,a,b)   asm("fma.rn.f32x2 %0,%1,%2,%0;" : "+l"(d) : "l"(a), "l"(b))

// ---------------- farthest point sampling (v6, unchanged) -------------------
__global__ void __launch_bounds__(1024) fps_k(const float* __restrict__ xyz,
                                              float* __restrict__ out) {
    extern __shared__ float fsm[];
    float* cxs = fsm; float* cys = fsm + NN; float* czs = fsm + 2 * NN;
    __shared__ unsigned sd[2][32], si[2][32];
    const int b = blockIdx.x, t = threadIdx.x, lane = t & 31, wrp = t >> 5;
    const float* xb = xyz + b * 3 * NN;
    float mind[4];
    unsigned long long px2[2], py2[2], pz2[2];
    {
        float px[4], py[4], pz[4];
#pragma unroll
        for (int j = 0; j < 4; j++) {
            int i = t + 1024 * j;
            px[j] = xb[i]; py[j] = xb[NN + i]; pz[j] = xb[2 * NN + i];
            cxs[i] = px[j]; cys[i] = py[j]; czs[i] = pz[j];
            mind[j] = 1e10f;
        }
#pragma unroll
        for (int g = 0; g < 2; g++) {
            PACKF2(px2[g], px[2 * g], px[2 * g + 1]);
            PACKF2(py2[g], py[2 * g], py[2 * g + 1]);
            PACKF2(pz2[g], pz[2 * g], pz[2 * g + 1]);
        }
    }
    __syncthreads();
    int cur = 0;
    if (t == 0) {
        float x = cxs[0], y = cys[0], z = czs[0];
        g_cent[b * SS * 3 + 0] = x; g_cent[b * SS * 3 + 1] = y; g_cent[b * SS * 3 + 2] = z;
        out[b * 3 * SS + 0] = x; out[b * 3 * SS + SS] = y; out[b * 3 * SS + 2 * SS] = z;
    }
    for (int it = 0; it < SS - 1; ++it) {
        const int buf = it & 1;
        float cx = cxs[cur], cy = cys[cur], cz = czs[cur];
        unsigned long long ncx2, ncy2, ncz2;
        {
            float nx = -cx, ny = -cy, nz = -cz;
            PACKF2(ncx2, nx, nx); PACKF2(ncy2, ny, ny); PACKF2(ncz2, nz, nz);
        }
#pragma unroll
        for (int g = 0; g < 2; g++) {
            unsigned long long dx2, dy2, dz2, qx, qy, qz, s01, s2;
            ADDF2(dx2, px2[g], ncx2);
            ADDF2(dy2, py2[g], ncy2);
            ADDF2(dz2, pz2[g], ncz2);
            MULF2(qx, dx2, dx2); MULF2(qy, dy2, dy2); MULF2(qz, dz2, dz2);
            ADDF2(s01, qx, qy); ADDF2(s2, s01, qz);
            float d0, d1; UNPACKF2(d0, d1, s2);
            mind[2 * g]     = fminf(mind[2 * g], d0);
            mind[2 * g + 1] = fminf(mind[2 * g + 1], d1);
        }
        bool a01 = mind[0] >= mind[1];
        float m0 = a01 ? mind[0] : mind[1]; int j0 = a01 ? 0 : 1;
        bool a23 = mind[2] >= mind[3];
        float m1 = a23 ? mind[2] : mind[3]; int j1 = a23 ? 2 : 3;
        bool af = m0 >= m1;
        float bd = af ? m0 : m1; int bj = af ? j0 : j1;
        int bi = t + 1024 * bj;
        unsigned ub = __float_as_uint(bd);
        unsigned wm = __reduce_max_sync(0xffffffffu, ub);
        unsigned cand = (ub == wm) ? (unsigned)bi : 0x7fffffffu;
        unsigned wi = __reduce_min_sync(0xffffffffu, cand);
        if (lane == 0) { sd[buf][wrp] = wm; si[buf][wrp] = wi; }
        __syncthreads();
        {
            unsigned d = sd[buf][lane];
            unsigned i = si[buf][lane];
            unsigned M = __reduce_max_sync(0xffffffffu, d);
            unsigned c2 = (d == M) ? i : 0x7fffffffu;
            cur = (int)__reduce_min_sync(0xffffffffu, c2);
        }
        if (t == 0) {
            int six = b * SS + it + 1;
            float x = cxs[cur], y = cys[cur], z = czs[cur];
            g_cent[six * 3 + 0] = x; g_cent[six * 3 + 1] = y; g_cent[six * 3 + 2] = z;
            out[b * 3 * SS + (it + 1)] = x;
            out[b * 3 * SS + SS + (it + 1)] = y;
            out[b * 3 * SS + 2 * SS + (it + 1)] = z;
        }
    }
}

// ---------------- fused ball query + gather + layer0 (9->64) + stats -------
__global__ void __launch_bounds__(256) ball_layer0_k(const float* __restrict__ xyz,
                                                     const float* __restrict__ pts,
                                                     const float* __restrict__ w0,
                                                     const float* __restrict__ b0) {
    extern __shared__ float dsm[];
    float4* p4 = reinterpret_cast<float4*>(dsm);
    float* f_s = dsm + 16384;
    unsigned long long* ws8 = reinterpret_cast<unsigned long long*>(dsm + 16384 + 2304);
    float* ps_w = dsm + 16384 + 2304 + 1152;
    float* pq_w = ps_w + 512;
    float* bs   = pq_w + 512;
    int*   idx_s = reinterpret_cast<int*>(bs + 64);
    const int t = threadIdx.x, lane = t & 31, wrp = t >> 5;
    const int b = blockIdx.x >> 7;
    const int sbase = (blockIdx.x & 127) * 8;
    const int pt = blockIdx.x * 256;
    const float* xb = xyz + b * 3 * NN;
    const float* pb = pts + b * 6 * NN;

    for (int i = t; i < NN; i += 256) {
        float x = xb[i], y = xb[NN + i], z = xb[2 * NN + i];
        float ps = __fadd_rn(__fadd_rn(__fmul_rn(x, x), __fmul_rn(y, y)),
                             __fmul_rn(z, z));
        p4[i] = make_float4(x, y, z, ps);
    }
    for (int e = t; e < 576; e += 256) {
        int o = e / 9, k = e % 9;
        float wv = w0[e];
        unsigned long long wd; PACKF2(wd, wv, wv);
        ws8[k * 64 + (o ^ (k & 7))] = wd;
    }
    if (t < 64) bs[t] = b0[t];
    __syncthreads();

    {
        const float R2 = (float)(0.4 * 0.4);
        int s = sbase + wrp;
        int gs = b * SS + s;
        float cx = g_cent[gs * 3], cy = g_cent[gs * 3 + 1], cz = g_cent[gs * 3 + 2];
        float cs = __fadd_rn(__fadd_rn(__fmul_rn(cx, cx), __fmul_rn(cy, cy)),
                             __fmul_rn(cz, cz));
        int* ob = idx_s + wrp * NSAMP;
        int count = 0, first = 0;
        for (int base = 0; base < NN && count < NSAMP; base += 32) {
            float4 p = p4[base + lane];
            float dot = __fadd_rn(__fadd_rn(__fmul_rn(cx, p.x), __fmul_rn(cy, p.y)),
                                  __fmul_rn(cz, p.z));
            float d = __fadd_rn(__fadd_rn(__fmul_rn(-2.f, dot), cs), p.w);
            bool isin = !(d > R2);
            unsigned m = __ballot_sync(0xffffffffu, isin);
            if (count == 0 && m) first = base + __ffs(m) - 1;
            int rank = count + __popc(m & ((1u << lane) - 1u));
            if (isin && rank < NSAMP) ob[rank] = base + lane;
            count += __popc(m);
        }
        if (count < NSAMP) {
            for (int r = count + lane; r < NSAMP; r += 32) ob[r] = first;
        }
    }
    __syncthreads();

    {
        int ci = t >> 5;
        int gs = b * SS + sbase + ci;
        int i = idx_s[t];
        float4 P = p4[i];
        f_s[0 * 256 + t] = P.x - g_cent[gs * 3 + 0];
        f_s[1 * 256 + t] = P.y - g_cent[gs * 3 + 1];
        f_s[2 * 256 + t] = P.z - g_cent[gs * 3 + 2];
#pragma unroll
        for (int c = 0; c < 6; c++) f_s[(3 + c) * 256 + t] = pb[c * NN + i];
    }
    __syncthreads();

    int og = t & 7, pg = t >> 3;
    unsigned long long acc2[8][4];
#pragma unroll
    for (int a = 0; a < 8; a++)
#pragma unroll
        for (int j = 0; j < 4; j++) acc2[a][j] = 0ull;
    const ulonglong2* in8 = reinterpret_cast<const ulonglong2*>(f_s);
#pragma unroll
    for (int k = 0; k < 9; k++) {
        unsigned long long wv2[8];
#pragma unroll
        for (int oi = 0; oi < 8; oi++)
            wv2[oi] = ws8[k * 64 + ((oi * 8 + og) ^ (k & 7))];
        ulonglong2 A0 = in8[k * 64 + pg * 2];
        ulonglong2 A1 = in8[k * 64 + pg * 2 + 1];
#pragma unroll
        for (int oi = 0; oi < 8; oi++) {
            FMAF2(acc2[oi][0], wv2[oi], A0.x);
            FMAF2(acc2[oi][1], wv2[oi], A0.y);
            FMAF2(acc2[oi][2], wv2[oi], A1.x);
            FMAF2(acc2[oi][3], wv2[oi], A1.y);
        }
    }
#pragma unroll
    for (int oi = 0; oi < 8; oi++) {
        int o = oi * 8 + og;
        float bo = bs[o];
        float v[8];
#pragma unroll
        for (int j = 0; j < 4; j++) {
            float a, bq; UNPACKF2(a, bq, acc2[oi][j]);
            v[2 * j] = a + bo; v[2 * j + 1] = bq + bo;
        }
        float s = 0.f, q = 0.f;
#pragma unroll
        for (int p = 0; p < 8; p++) { s += v[p]; q = fmaf(v[p], v[p], q); }
        float* orow = g_h0 + (size_t)o * MM + pt + pg * 8;
        *reinterpret_cast<float4*>(orow)     = make_float4(v[0], v[1], v[2], v[3]);
        *reinterpret_cast<float4*>(orow + 4) = make_float4(v[4], v[5], v[6], v[7]);
#pragma unroll
        for (int off = 8; off < 32; off <<= 1) {
            s += __shfl_xor_sync(0xffffffffu, s, off);
            q += __shfl_xor_sync(0xffffffffu, q, off);
        }
        if (lane < 8) {
            ps_w[wrp * 64 + oi * 8 + lane] = s;
            pq_w[wrp * 64 + oi * 8 + lane] = q;
        }
    }
    __syncthreads();
    if (t < 64) {
        float s = 0.f, q = 0.f;
#pragma unroll
        for (int wk = 0; wk < 8; wk++) { s += ps_w[wk * 64 + t]; q += pq_w[wk * 64 + t]; }
        g_part_s[(size_t)t * MAXBLK + blockIdx.x] = s;
        g_part_q[(size_t)t * MAXBLK + blockIdx.x] = q;
    }
}

// ---------------- reduce partials + finalize scale/shift (fused) -----------
__global__ void __launch_bounds__(256) reduce_fin_k(int nblk, int off,
                                                    const float* __restrict__ gw,
                                                    const float* __restrict__ bw) {
    int c = blockIdx.x;
    const float* ps = g_part_s + (size_t)c * MAXBLK;
    const float* pq = g_part_q + (size_t)c * MAXBLK;
    float s = 0.f, q = 0.f;
    for (int i = threadIdx.x; i < nblk; i += 256) { s += ps[i]; q += pq[i]; }
#pragma unroll
    for (int o = 16; o; o >>= 1) {
        s += __shfl_xor_sync(0xffffffffu, s, o);
        q += __shfl_xor_sync(0xffffffffu, q, o);
    }
    __shared__ float sred[8], qred[8];
    if ((threadIdx.x & 31) == 0) { sred[threadIdx.x >> 5] = s; qred[threadIdx.x >> 5] = q; }
    __syncthreads();
    if (threadIdx.x == 0) {
        float st = 0.f, qt = 0.f;
        for (int w = 0; w < 8; w++) { st += sred[w]; qt += qred[w]; }
        float mu = st / (float)MM;
        float var = qt / (float)MM - mu * mu;
        float istd = rsqrtf(var + 1e-5f);
        float sc = gw[c] * istd;
        g_scale[off + c] = sc;
        g_shift[off + c] = bw[c] - mu * sc;
    }
}

// ---------------- GEMM layers (64 -> OUTC), BN+ReLU fused on input load ----
// Round-12 proven inner loop: padded-linear weight smem w_s[o*65+k], scalar
// weight LDS (broadcast, 1 wavefront per 8-out group), f32x2 pair rebuilt in
// a register. TP per layer chosen for 3 blocks/SM on both:
//   gemm1: TP=128, OG=8,  PPT=4, smem ~53.5KB
//   gemm2: TP=64,  OG=16, PPT=4, smem ~65.3KB
template <int OUTC, int TP, bool WRITE>
__global__ void __launch_bounds__(256, 3)
gemm_k(const float* __restrict__ w, const float* __restrict__ bias) {
    constexpr int OG = OUTC / 8;
    constexpr int PPT = TP * OG / 256;    // 4 for both layers
    constexpr int GRP = TP / 32;          // sample groups per block
    constexpr int PGG = 32 / PPT;         // pgs per sample group
    const float* in = WRITE ? g_h0 : g_h1;
    const int soff  = WRITE ? 0 : 64;
    extern __shared__ float dsm[];
    float* in_s = dsm;                          // 64*TP floats
    float* w_s  = dsm + 64 * TP;                // OUTC*65 floats
    float* ps_w = w_s + OUTC * 65;              // 8*OUTC
    float* pq_w = ps_w + 8 * OUTC;              // 8*OUTC
    float* msm  = pq_w + 8 * OUTC;              // (256/OG)*OUTC if !WRITE
    int t = threadIdx.x, lane = t & 31, wrp = t >> 5;
    int pt = blockIdx.x * TP;
    for (int e = t; e < 64 * TP; e += 256) {
        int k = e / TP, p = e % TP;
        float v = in[(size_t)k * MM + pt + p];
        in_s[e] = fmaxf(fmaf(v, g_scale[soff + k], g_shift[soff + k]), 0.f);
    }
    for (int e = t; e < 64 * OUTC; e += 256) {
        int o = e >> 6, k = e & 63;             // w global (OUTC,64)
        w_s[o * 65 + k] = w[e];
    }
    __syncthreads();
    int og = t % OG, pg = t / OG;
    int wb[8];
#pragma unroll
    for (int oi = 0; oi < 8; oi++) wb[oi] = (oi * OG + og) * 65;
    unsigned long long acc2[8][PPT / 2];
#pragma unroll
    for (int a = 0; a < 8; a++)
#pragma unroll
        for (int j = 0; j < PPT / 2; j++) acc2[a][j] = 0ull;
    const ulonglong2* in8 = reinterpret_cast<const ulonglong2*>(in_s);
#pragma unroll 4
    for (int k = 0; k < 64; k++) {
        unsigned long long wv2[8];
#pragma unroll
        for (int oi = 0; oi < 8; oi++) {
            float wv = w_s[wb[oi] + k];
            PACKF2(wv2[oi], wv, wv);
        }
        ulonglong2 A[PPT / 4];
#pragma unroll
        for (int j = 0; j < PPT / 4; j++)
            A[j] = in8[k * (TP / 4) + pg * (PPT / 4) + j];
#pragma unroll
        for (int oi = 0; oi < 8; oi++)
#pragma unroll
            for (int j = 0; j < PPT / 4; j++) {
                FMAF2(acc2[oi][2 * j],     wv2[oi], A[j].x);
                FMAF2(acc2[oi][2 * j + 1], wv2[oi], A[j].y);
            }
    }
#pragma unroll
    for (int oi = 0; oi < 8; oi++) {
        int o = oi * OG + og;
        float bo = bias[o];
        float v[PPT];
#pragma unroll
        for (int j = 0; j < PPT / 2; j++) {
            float a, bq; UNPACKF2(a, bq, acc2[oi][j]);
            v[2 * j] = a + bo; v[2 * j + 1] = bq + bo;
        }
        float s = 0.f, q = 0.f;
#pragma unroll
        for (int p = 0; p < PPT; p++) { s += v[p]; q = fmaf(v[p], v[p], q); }
        if (WRITE) {
            float* orow = g_h1 + (size_t)o * MM + pt + pg * PPT;
#pragma unroll
            for (int j = 0; j < PPT / 4; j++)
                *reinterpret_cast<float4*>(orow + 4 * j) =
                    make_float4(v[4 * j], v[4 * j + 1], v[4 * j + 2], v[4 * j + 3]);
        } else {
            float m = v[0];
#pragma unroll
            for (int p = 1; p < PPT; p++) m = fmaxf(m, v[p]);
            msm[pg * OUTC + o] = m;
        }
#pragma unroll
        for (int off = OG; off < 32; off <<= 1) {
            s += __shfl_xor_sync(0xffffffffu, s, off);
            q += __shfl_xor_sync(0xffffffffu, q, off);
        }
        if (lane < OG) {
            ps_w[wrp * OUTC + oi * OG + lane] = s;
            pq_w[wrp * OUTC + oi * OG + lane] = q;
        }
    }
    __syncthreads();
    if (t < OUTC) {
        float s = 0.f, q = 0.f;
#pragma unroll
        for (int wk = 0; wk < 8; wk++) {
            s += ps_w[wk * OUTC + t];
            q += pq_w[wk * OUTC + t];
        }
        g_part_s[(size_t)t * MAXBLK + blockIdx.x] = s;
        g_part_q[(size_t)t * MAXBLK + blockIdx.x] = q;
    }
    if (!WRITE) {
        // GRP sample-groups of 32 positions; each = PGG consecutive pgs
        for (int tt = t; tt < GRP * OUTC; tt += 256) {
            int o = tt % OUTC, grp = tt / OUTC;
            float m = msm[(grp * PGG) * OUTC + o];
#pragma unroll
            for (int j = 1; j < PGG; j++)
                m = fmaxf(m, msm[(grp * PGG + j) * OUTC + o]);
            g_max[(size_t)o * 16384 + blockIdx.x * GRP + grp] = m;
        }
    }
}

// ---------------- BN+ReLU on pooled maxes ----------------------------------
__global__ void __launch_bounds__(256) pool2_k(float* __restrict__ out) {
    int g = blockIdx.x * 256 + threadIdx.x;
    int b = g >> 17, o = (g >> 10) & 127, s = g & 1023;
    float v = fmaf(g_max[o * 16384 + b * 1024 + s], g_scale[128 + o], g_shift[128 + o]);
    out[BB * 3 * SS + g] = fmaxf(v, 0.f);
}

// ---------------- launch ---------------------------------------------------
extern "C" void kernel_launch(void* const* d_in, const int* in_sizes, int n_in,
                              void* d_out, int out_size) {
    const float* xyz = (const float*)d_in[0];
    const float* pts = (const float*)d_in[1];
    const float* w0  = (const float*)d_in[2];
    const float* b0  = (const float*)d_in[3];
    const float* g0  = (const float*)d_in[4];
    const float* be0 = (const float*)d_in[5];
    const float* w1  = (const float*)d_in[6];
    const float* b1  = (const float*)d_in[7];
    const float* g1  = (const float*)d_in[8];
    const float* be1 = (const float*)d_in[9];
    const float* w2  = (const float*)d_in[10];
    const float* b2  = (const float*)d_in[11];
    const float* g2  = (const float*)d_in[12];
    const float* be2 = (const float*)d_in[13];
    float* out = (float*)d_out;

    constexpr int SMB = 21184 * 4;                                   // 84736
    // gemm1: in 64*128 + w 64*65 + ps/pq 16*64                = 53504 B (3/SM)
    constexpr int SM1 = (64 * 128 + 64 * 65 + 16 * 64) * 4;
    // gemm2: in 64*64 + w 128*65 + ps/pq 16*128 + msm 16*128  = 66816 B (3/SM)
    constexpr int SM2 = (64 * 64 + 128 * 65 + 16 * 128 + 16 * 128) * 4;

    cudaFuncSetAttribute(fps_k, cudaFuncAttributeMaxDynamicSharedMemorySize, 3 * NN * 4);
    cudaFuncSetAttribute(ball_layer0_k, cudaFuncAttributeMaxDynamicSharedMemorySize, SMB);
    cudaFuncSetAttribute((const void*)gemm_k<64, 128, true>,
                         cudaFuncAttributeMaxDynamicSharedMemorySize, SM1);
    cudaFuncSetAttribute((const void*)gemm_k<128, 64, false>,
                         cudaFuncAttributeMaxDynamicSharedMemorySize, SM2);

    fps_k<<<BB, 1024, 3 * NN * 4>>>(xyz, out);               // 1
    ball_layer0_k<<<MM / 256, 256, SMB>>>(xyz, pts, w0, b0); // 2
    reduce_fin_k<<<64, 256>>>(MM / 256, 0, g0, be0);         // 3
    gemm_k<64, 128, true><<<MM / 128, 256, SM1>>>(w1, b1);   // 4  <- profiled
    reduce_fin_k<<<64, 256>>>(MM / 128, 64, g1, be1);        // 5
    gemm_k<128, 64, false><<<MM / 64, 256, SM2>>>(w2, b2);   // 6
    reduce_fin_k<<<128, 256>>>(MM / 64, 128, g2, be2);       // 7
    pool2_k<<<(BB * 128 * SS) / 256, 256>>>(out);            // 8
}

// round 15
// speedup vs baseline: 1.6373x; 1.6373x over previous
#include <cuda_runtime.h>

#define BB 16
#define NN 4096
#define SS 1024
#define NSAMP 32
#define MM (BB*SS*NSAMP)  // 524288
#define MAXBLK 8192

// ---------------- scratch (__device__ globals: no allocations allowed) ----
__device__ float g_cent[BB*SS*3];
__device__ float g_h0[64*MM];    // 134 MB
__device__ float g_h1[64*MM];    // 134 MB
__device__ float g_max[128*16384];
__device__ float g_part_s[128*MAXBLK];
__device__ float g_part_q[128*MAXBLK];
__device__ float g_scale[256];
__device__ float g_shift[256];

// packed f32x2 helpers (per-element IEEE rn — bit-identical to scalar rn ops)
#define PACKF2(o,a,b)  asm("mov.b64 %0,{%1,%2};"       : "=l"(o) : "f"(a), "f"(b))
#define UNPACKF2(a,b,i) asm("mov.b64 {%0,%1},%2;"      : "=f"(a), "=f"(b) : "l"(i))
#define ADDF2(o,a,b)   asm("add.rn.f32x2 %0,%1,%2;"    : "=l"(o) : "l"(a), "l"(b))
#define MULF2(o,a,b)   asm("mul.rn.f32x2 %0,%1,%2;"    : "=l"(o) : "l"(a), "l"(b))
#define FMAF2(d,a,b)   asm("fma.rn.f32x2 %0,%1,%2,%0;" : "+l"(d) : "l"(a), "l"(b))

// ---------------- farthest point sampling (v6, unchanged) -------------------
__global__ void __launch_bounds__(1024) fps_k(const float* __restrict__ xyz,
                                              float* __restrict__ out) {
    extern __shared__ float fsm[];
    float* cxs = fsm; float* cys = fsm + NN; float* czs = fsm + 2 * NN;
    __shared__ unsigned sd[2][32], si[2][32];
    const int b = blockIdx.x, t = threadIdx.x, lane = t & 31, wrp = t >> 5;
    const float* xb = xyz + b * 3 * NN;
    float mind[4];
    unsigned long long px2[2], py2[2], pz2[2];
    {
        float px[4], py[4], pz[4];
#pragma unroll
        for (int j = 0; j < 4; j++) {
            int i = t + 1024 * j;
            px[j] = xb[i]; py[j] = xb[NN + i]; pz[j] = xb[2 * NN + i];
            cxs[i] = px[j]; cys[i] = py[j]; czs[i] = pz[j];
            mind[j] = 1e10f;
        }
#pragma unroll
        for (int g = 0; g < 2; g++) {
            PACKF2(px2[g], px[2 * g], px[2 * g + 1]);
            PACKF2(py2[g], py[2 * g], py[2 * g + 1]);
            PACKF2(pz2[g], pz[2 * g], pz[2 * g + 1]);
        }
    }
    __syncthreads();
    int cur = 0;
    if (t == 0) {
        float x = cxs[0], y = cys[0], z = czs[0];
        g_cent[b * SS * 3 + 0] = x; g_cent[b * SS * 3 + 1] = y; g_cent[b * SS * 3 + 2] = z;
        out[b * 3 * SS + 0] = x; out[b * 3 * SS + SS] = y; out[b * 3 * SS + 2 * SS] = z;
    }
    for (int it = 0; it < SS - 1; ++it) {
        const int buf = it & 1;
        float cx = cxs[cur], cy = cys[cur], cz = czs[cur];
        unsigned long long ncx2, ncy2, ncz2;
        {
            float nx = -cx, ny = -cy, nz = -cz;
            PACKF2(ncx2, nx, nx); PACKF2(ncy2, ny, ny); PACKF2(ncz2, nz, nz);
        }
#pragma unroll
        for (int g = 0; g < 2; g++) {
            unsigned long long dx2, dy2, dz2, qx, qy, qz, s01, s2;
            ADDF2(dx2, px2[g], ncx2);
            ADDF2(dy2, py2[g], ncy2);
            ADDF2(dz2, pz2[g], ncz2);
            MULF2(qx, dx2, dx2); MULF2(qy, dy2, dy2); MULF2(qz, dz2, dz2);
            ADDF2(s01, qx, qy); ADDF2(s2, s01, qz);
            float d0, d1; UNPACKF2(d0, d1, s2);
            mind[2 * g]     = fminf(mind[2 * g], d0);
            mind[2 * g + 1] = fminf(mind[2 * g + 1], d1);
        }
        bool a01 = mind[0] >= mind[1];
        float m0 = a01 ? mind[0] : mind[1]; int j0 = a01 ? 0 : 1;
        bool a23 = mind[2] >= mind[3];
        float m1 = a23 ? mind[2] : mind[3]; int j1 = a23 ? 2 : 3;
        bool af = m0 >= m1;
        float bd = af ? m0 : m1; int bj = af ? j0 : j1;
        int bi = t + 1024 * bj;
        unsigned ub = __float_as_uint(bd);
        unsigned wm = __reduce_max_sync(0xffffffffu, ub);
        unsigned cand = (ub == wm) ? (unsigned)bi : 0x7fffffffu;
        unsigned wi = __reduce_min_sync(0xffffffffu, cand);
        if (lane == 0) { sd[buf][wrp] = wm; si[buf][wrp] = wi; }
        __syncthreads();
        {
            unsigned d = sd[buf][lane];
            unsigned i = si[buf][lane];
            unsigned M = __reduce_max_sync(0xffffffffu, d);
            unsigned c2 = (d == M) ? i : 0x7fffffffu;
            cur = (int)__reduce_min_sync(0xffffffffu, c2);
        }
        if (t == 0) {
            int six = b * SS + it + 1;
            float x = cxs[cur], y = cys[cur], z = czs[cur];
            g_cent[six * 3 + 0] = x; g_cent[six * 3 + 1] = y; g_cent[six * 3 + 2] = z;
            out[b * 3 * SS + (it + 1)] = x;
            out[b * 3 * SS + SS + (it + 1)] = y;
            out[b * 3 * SS + 2 * SS + (it + 1)] = z;
        }
    }
}

// ---------------- fused ball query + gather + layer0 (9->64) + stats -------
__global__ void __launch_bounds__(256) ball_layer0_k(const float* __restrict__ xyz,
                                                     const float* __restrict__ pts,
                                                     const float* __restrict__ w0,
                                                     const float* __restrict__ b0) {
    extern __shared__ float dsm[];
    float4* p4 = reinterpret_cast<float4*>(dsm);
    float* f_s = dsm + 16384;
    unsigned long long* ws8 = reinterpret_cast<unsigned long long*>(dsm + 16384 + 2304);
    float* ps_w = dsm + 16384 + 2304 + 1152;
    float* pq_w = ps_w + 512;
    float* bs   = pq_w + 512;
    int*   idx_s = reinterpret_cast<int*>(bs + 64);
    const int t = threadIdx.x, lane = t & 31, wrp = t >> 5;
    const int b = blockIdx.x >> 7;
    const int sbase = (blockIdx.x & 127) * 8;
    const int pt = blockIdx.x * 256;
    const float* xb = xyz + b * 3 * NN;
    const float* pb = pts + b * 6 * NN;

    for (int i = t; i < NN; i += 256) {
        float x = xb[i], y = xb[NN + i], z = xb[2 * NN + i];
        float ps = __fadd_rn(__fadd_rn(__fmul_rn(x, x), __fmul_rn(y, y)),
                             __fmul_rn(z, z));
        p4[i] = make_float4(x, y, z, ps);
    }
    for (int e = t; e < 576; e += 256) {
        int o = e / 9, k = e % 9;
        float wv = w0[e];
        unsigned long long wd; PACKF2(wd, wv, wv);
        ws8[k * 64 + (o ^ (k & 7))] = wd;
    }
    if (t < 64) bs[t] = b0[t];
    __syncthreads();

    {
        const float R2 = (float)(0.4 * 0.4);
        int s = sbase + wrp;
        int gs = b * SS + s;
        float cx = g_cent[gs * 3], cy = g_cent[gs * 3 + 1], cz = g_cent[gs * 3 + 2];
        float cs = __fadd_rn(__fadd_rn(__fmul_rn(cx, cx), __fmul_rn(cy, cy)),
                             __fmul_rn(cz, cz));
        int* ob = idx_s + wrp * NSAMP;
        int count = 0, first = 0;
        for (int base = 0; base < NN && count < NSAMP; base += 32) {
            float4 p = p4[base + lane];
            float dot = __fadd_rn(__fadd_rn(__fmul_rn(cx, p.x), __fmul_rn(cy, p.y)),
                                  __fmul_rn(cz, p.z));
            float d = __fadd_rn(__fadd_rn(__fmul_rn(-2.f, dot), cs), p.w);
            bool isin = !(d > R2);
            unsigned m = __ballot_sync(0xffffffffu, isin);
            if (count == 0 && m) first = base + __ffs(m) - 1;
            int rank = count + __popc(m & ((1u << lane) - 1u));
            if (isin && rank < NSAMP) ob[rank] = base + lane;
            count += __popc(m);
        }
        if (count < NSAMP) {
            for (int r = count + lane; r < NSAMP; r += 32) ob[r] = first;
        }
    }
    __syncthreads();

    {
        int ci = t >> 5;
        int gs = b * SS + sbase + ci;
        int i = idx_s[t];
        float4 P = p4[i];
        f_s[0 * 256 + t] = P.x - g_cent[gs * 3 + 0];
        f_s[1 * 256 + t] = P.y - g_cent[gs * 3 + 1];
        f_s[2 * 256 + t] = P.z - g_cent[gs * 3 + 2];
#pragma unroll
        for (int c = 0; c < 6; c++) f_s[(3 + c) * 256 + t] = pb[c * NN + i];
    }
    __syncthreads();

    int og = t & 7, pg = t >> 3;
    unsigned long long acc2[8][4];
#pragma unroll
    for (int a = 0; a < 8; a++)
#pragma unroll
        for (int j = 0; j < 4; j++) acc2[a][j] = 0ull;
    const ulonglong2* in8 = reinterpret_cast<const ulonglong2*>(f_s);
#pragma unroll
    for (int k = 0; k < 9; k++) {
        unsigned long long wv2[8];
#pragma unroll
        for (int oi = 0; oi < 8; oi++)
            wv2[oi] = ws8[k * 64 + ((oi * 8 + og) ^ (k & 7))];
        ulonglong2 A0 = in8[k * 64 + pg * 2];
        ulonglong2 A1 = in8[k * 64 + pg * 2 + 1];
#pragma unroll
        for (int oi = 0; oi < 8; oi++) {
            FMAF2(acc2[oi][0], wv2[oi], A0.x);
            FMAF2(acc2[oi][1], wv2[oi], A0.y);
            FMAF2(acc2[oi][2], wv2[oi], A1.x);
            FMAF2(acc2[oi][3], wv2[oi], A1.y);
        }
    }
#pragma unroll
    for (int oi = 0; oi < 8; oi++) {
        int o = oi * 8 + og;
        float bo = bs[o];
        float v[8];
#pragma unroll
        for (int j = 0; j < 4; j++) {
            float a, bq; UNPACKF2(a, bq, acc2[oi][j]);
            v[2 * j] = a + bo; v[2 * j + 1] = bq + bo;
        }
        float s = 0.f, q = 0.f;
#pragma unroll
        for (int p = 0; p < 8; p++) { s += v[p]; q = fmaf(v[p], v[p], q); }
        float* orow = g_h0 + (size_t)o * MM + pt + pg * 8;
        *reinterpret_cast<float4*>(orow)     = make_float4(v[0], v[1], v[2], v[3]);
        *reinterpret_cast<float4*>(orow + 4) = make_float4(v[4], v[5], v[6], v[7]);
#pragma unroll
        for (int off = 8; off < 32; off <<= 1) {
            s += __shfl_xor_sync(0xffffffffu, s, off);
            q += __shfl_xor_sync(0xffffffffu, q, off);
        }
        if (lane < 8) {
            ps_w[wrp * 64 + oi * 8 + lane] = s;
            pq_w[wrp * 64 + oi * 8 + lane] = q;
        }
    }
    __syncthreads();
    if (t < 64) {
        float s = 0.f, q = 0.f;
#pragma unroll
        for (int wk = 0; wk < 8; wk++) { s += ps_w[wk * 64 + t]; q += pq_w[wk * 64 + t]; }
        g_part_s[(size_t)t * MAXBLK + blockIdx.x] = s;
        g_part_q[(size_t)t * MAXBLK + blockIdx.x] = q;
    }
}

// ---------------- reduce partials + finalize scale/shift (fused) -----------
__global__ void __launch_bounds__(256) reduce_fin_k(int nblk, int off,
                                                    const float* __restrict__ gw,
                                                    const float* __restrict__ bw) {
    int c = blockIdx.x;
    const float* ps = g_part_s + (size_t)c * MAXBLK;
    const float* pq = g_part_q + (size_t)c * MAXBLK;
    float s = 0.f, q = 0.f;
    for (int i = threadIdx.x; i < nblk; i += 256) { s += ps[i]; q += pq[i]; }
#pragma unroll
    for (int o = 16; o; o >>= 1) {
        s += __shfl_xor_sync(0xffffffffu, s, o);
        q += __shfl_xor_sync(0xffffffffu, q, o);
    }
    __shared__ float sred[8], qred[8];
    if ((threadIdx.x & 31) == 0) { sred[threadIdx.x >> 5] = s; qred[threadIdx.x >> 5] = q; }
    __syncthreads();
    if (threadIdx.x == 0) {
        float st = 0.f, qt = 0.f;
        for (int w = 0; w < 8; w++) { st += sred[w]; qt += qred[w]; }
        float mu = st / (float)MM;
        float var = qt / (float)MM - mu * mu;
        float istd = rsqrtf(var + 1e-5f);
        float sc = gw[c] * istd;
        g_scale[off + c] = sc;
        g_shift[off + c] = bw[c] - mu * sc;
    }
}

// ---------------- GEMM layers (64 -> OUTC), BN+ReLU fused on input load ----
// Per-layer best-measured variants:
//   gemm1 (WRITE=true):  scalar weight LDS, pad 65 (round-12: 165us), 3/SM
//   gemm2 (WRITE=false): float4 weight LDS over 4 k-steps, pad 68
//                        (round-13 config inside best total), 2/SM
// TP=128 both. FMA order per accumulator identical to measured rounds.
template <int OUTC, bool WRITE>
__global__ void __launch_bounds__(256, WRITE ? 3 : 2)
gemm_k(const float* __restrict__ w, const float* __restrict__ bias) {
    constexpr int TP = 128;
    constexpr int OG = OUTC / 8;          // 8 | 16
    constexpr int PPT = TP * OG / 256;    // 4 | 8 positions per thread
    constexpr int PAD = WRITE ? 65 : 68;
    const float* in = WRITE ? g_h0 : g_h1;
    const int soff  = WRITE ? 0 : 64;
    extern __shared__ float dsm[];
    float* in_s = dsm;                          // 64*TP floats
    float* w_s  = dsm + 64 * TP;                // OUTC*PAD floats
    float* ps_w = w_s + OUTC * PAD;             // 8*OUTC
    float* pq_w = ps_w + 8 * OUTC;              // 8*OUTC
    float* msm  = pq_w + 8 * OUTC;              // 16*OUTC if !WRITE
    int t = threadIdx.x, lane = t & 31, wrp = t >> 5;
    int pt = blockIdx.x * TP;
    for (int e = t; e < 64 * TP; e += 256) {
        int k = e / TP, p = e % TP;
        float v = in[(size_t)k * MM + pt + p];
        in_s[e] = fmaxf(fmaf(v, g_scale[soff + k], g_shift[soff + k]), 0.f);
    }
    for (int e = t; e < 64 * OUTC; e += 256) {
        int o = e >> 6, k = e & 63;             // w global (OUTC,64)
        w_s[o * PAD + k] = w[e];
    }
    __syncthreads();
    int og = t % OG, pg = t / OG;
    int wb[8];
#pragma unroll
    for (int oi = 0; oi < 8; oi++) wb[oi] = (oi * OG + og) * PAD;
    unsigned long long acc2[8][PPT / 2];
#pragma unroll
    for (int a = 0; a < 8; a++)
#pragma unroll
        for (int j = 0; j < PPT / 2; j++) acc2[a][j] = 0ull;
    const ulonglong2* in8 = reinterpret_cast<const ulonglong2*>(in_s);
    if (WRITE) {
        // scalar weight loads (round-12 proven)
#pragma unroll 4
        for (int k = 0; k < 64; k++) {
            unsigned long long wv2[8];
#pragma unroll
            for (int oi = 0; oi < 8; oi++) {
                float wv = w_s[wb[oi] + k];
                PACKF2(wv2[oi], wv, wv);
            }
            ulonglong2 A[PPT / 4];
#pragma unroll
            for (int j = 0; j < PPT / 4; j++)
                A[j] = in8[k * (TP / 4) + pg * (PPT / 4) + j];
#pragma unroll
            for (int oi = 0; oi < 8; oi++)
#pragma unroll
                for (int j = 0; j < PPT / 4; j++) {
                    FMAF2(acc2[oi][2 * j],     wv2[oi], A[j].x);
                    FMAF2(acc2[oi][2 * j + 1], wv2[oi], A[j].y);
                }
        }
    } else {
        // float4 weight loads over 4 k-steps (round-13 proven)
#pragma unroll 2
        for (int kk = 0; kk < 64; kk += 4) {
            float4 wv4[8];
#pragma unroll
            for (int oi = 0; oi < 8; oi++)
                wv4[oi] = *reinterpret_cast<const float4*>(w_s + wb[oi] + kk);
#pragma unroll
            for (int dk = 0; dk < 4; dk++) {
                const int k = kk + dk;
                ulonglong2 A[PPT / 4];
#pragma unroll
                for (int j = 0; j < PPT / 4; j++)
                    A[j] = in8[k * (TP / 4) + pg * (PPT / 4) + j];
#pragma unroll
                for (int oi = 0; oi < 8; oi++) {
                    float wv = reinterpret_cast<const float*>(&wv4[oi])[dk];
                    unsigned long long wv2; PACKF2(wv2, wv, wv);
#pragma unroll
                    for (int j = 0; j < PPT / 4; j++) {
                        FMAF2(acc2[oi][2 * j],     wv2, A[j].x);
                        FMAF2(acc2[oi][2 * j + 1], wv2, A[j].y);
                    }
                }
            }
        }
    }
#pragma unroll
    for (int oi = 0; oi < 8; oi++) {
        int o = oi * OG + og;
        float bo = bias[o];
        float v[PPT];
#pragma unroll
        for (int j = 0; j < PPT / 2; j++) {
            float a, bq; UNPACKF2(a, bq, acc2[oi][j]);
            v[2 * j] = a + bo; v[2 * j + 1] = bq + bo;
        }
        float s = 0.f, q = 0.f;
#pragma unroll
        for (int p = 0; p < PPT; p++) { s += v[p]; q = fmaf(v[p], v[p], q); }
        if (WRITE) {
            float* orow = g_h1 + (size_t)o * MM + pt + pg * PPT;
#pragma unroll
            for (int j = 0; j < PPT / 4; j++)
                *reinterpret_cast<float4*>(orow + 4 * j) =
                    make_float4(v[4 * j], v[4 * j + 1], v[4 * j + 2], v[4 * j + 3]);
        } else {
            float m = v[0];
#pragma unroll
            for (int p = 1; p < PPT; p++) m = fmaxf(m, v[p]);
            msm[pg * OUTC + o] = m;
        }
#pragma unroll
        for (int off = OG; off < 32; off <<= 1) {
            s += __shfl_xor_sync(0xffffffffu, s, off);
            q += __shfl_xor_sync(0xffffffffu, q, off);
        }
        if (lane < OG) {
            ps_w[wrp * OUTC + oi * OG + lane] = s;
            pq_w[wrp * OUTC + oi * OG + lane] = q;
        }
    }
    __syncthreads();
    if (t < OUTC) {
        float s = 0.f, q = 0.f;
#pragma unroll
        for (int wk = 0; wk < 8; wk++) {
            s += ps_w[wk * OUTC + t];
            q += pq_w[wk * OUTC + t];
        }
        g_part_s[(size_t)t * MAXBLK + blockIdx.x] = s;
        g_part_q[(size_t)t * MAXBLK + blockIdx.x] = q;
    }
    if (!WRITE) {
        // TP=128 positions = 4 sample-groups of 32 = 4 consecutive pg's each
        for (int tt = t; tt < 4 * OUTC; tt += 256) {
            int o = tt & (OUTC - 1), grp = tt / OUTC;
            float m = msm[(grp * 4) * OUTC + o];
#pragma unroll
            for (int j = 1; j < 4; j++)
                m = fmaxf(m, msm[(grp * 4 + j) * OUTC + o]);
            g_max[(size_t)o * 16384 + blockIdx.x * 4 + grp] = m;
        }
    }
}

// ---------------- BN+ReLU on pooled maxes ----------------------------------
__global__ void __launch_bounds__(256) pool2_k(float* __restrict__ out) {
    int g = blockIdx.x * 256 + threadIdx.x;
    int b = g >> 17, o = (g >> 10) & 127, s = g & 1023;
    float v = fmaf(g_max[o * 16384 + b * 1024 + s], g_scale[128 + o], g_shift[128 + o]);
    out[BB * 3 * SS + g] = fmaxf(v, 0.f);
}

// ---------------- launch ---------------------------------------------------
extern "C" void kernel_launch(void* const* d_in, const int* in_sizes, int n_in,
                              void* d_out, int out_size) {
    const float* xyz = (const float*)d_in[0];
    const float* pts = (const float*)d_in[1];
    const float* w0  = (const float*)d_in[2];
    const float* b0  = (const float*)d_in[3];
    const float* g0  = (const float*)d_in[4];
    const float* be0 = (const float*)d_in[5];
    const float* w1  = (const float*)d_in[6];
    const float* b1  = (const float*)d_in[7];
    const float* g1  = (const float*)d_in[8];
    const float* be1 = (const float*)d_in[9];
    const float* w2  = (const float*)d_in[10];
    const float* b2  = (const float*)d_in[11];
    const float* g2  = (const float*)d_in[12];
    const float* be2 = (const float*)d_in[13];
    float* out = (float*)d_out;

    constexpr int SMB = 21184 * 4;                                   // 84736
    // gemm1: in 64*128 + w 64*65 + ps/pq 16*64 = 53504 B (3/SM)
    constexpr int SM1 = (64 * 128 + 64 * 65 + 16 * 64) * 4;
    // gemm2: in 64*128 + w 128*68 + ps/pq 16*128 + msm 16*128 = 83968 B (2/SM)
    constexpr int SM2 = (64 * 128 + 128 * 68 + 16 * 128 + 16 * 128) * 4;

    cudaFuncSetAttribute(fps_k, cudaFuncAttributeMaxDynamicSharedMemorySize, 3 * NN * 4);
    cudaFuncSetAttribute(ball_layer0_k, cudaFuncAttributeMaxDynamicSharedMemorySize, SMB);
    cudaFuncSetAttribute((const void*)gemm_k<64, true>,
                         cudaFuncAttributeMaxDynamicSharedMemorySize, SM1);
    cudaFuncSetAttribute((const void*)gemm_k<128, false>,
                         cudaFuncAttributeMaxDynamicSharedMemorySize, SM2);

    fps_k<<<BB, 1024, 3 * NN * 4>>>(xyz, out);               // 1
    ball_layer0_k<<<MM / 256, 256, SMB>>>(xyz, pts, w0, b0); // 2
    reduce_fin_k<<<64, 256>>>(MM / 256, 0, g0, be0);         // 3
    gemm_k<64, true><<<MM / 128, 256, SM1>>>(w1, b1);        // 4  <- profiled
    reduce_fin_k<<<64, 256>>>(MM / 128, 64, g1, be1);        // 5
    gemm_k<128, false><<<MM / 128, 256, SM2>>>(w2, b2);      // 6
    reduce_fin_k<<<128, 256>>>(MM / 128, 128, g2, be2);      // 7
    pool2_k<<<(BB * 128 * SS) / 256, 256>>>(out);            // 8
}